// round 11
// baseline (speedup 1.0000x reference)
#include <cuda_runtime.h>
#include <cuda_bf16.h>
#include <cuda_fp16.h>
#include <mma.h>
#include <math.h>
#include <cstdint>

using namespace nvcuda;

#define D 128
#define MAX_N 100096
#define CAP 96
#define OVF_CAP 8192
#define BROWS 128
#define PK 64                   // K panel size

// Scratch (allocation-free rule: __device__ globals).
__device__ __half  g_Y[(size_t)MAX_N * D];      // Y = H * W' in fp16
__device__ float   g_c[D];                      // c = t.W + b
__device__ int     g_cnt[MAX_N];                // per-node edge count
__device__ int2    g_edge[(size_t)MAX_N * CAP]; // edge buckets (src, w-bits)
__device__ int     g_ovf_cnt;                   // overflow list count
__device__ int4    g_ovf[OVF_CAP];              // overflow edges (dst, src, w-bits, 0)

// ---------------------------------------------------------------------------
__global__ void zero_kernel(int n) {
    int i = blockIdx.x * blockDim.x + threadIdx.x;
    if (i < n) g_cnt[i] = 0;
    if (i == 0) g_ovf_cnt = 0;
}

// c[j] = bias[j] + sum_k (beta_k - mean_k*s_k) * W[k][j]
__global__ void prep_c_kernel(const float* __restrict__ W,
                              const float* __restrict__ bias,
                              const float* __restrict__ gamma,
                              const float* __restrict__ beta,
                              const float* __restrict__ mean,
                              const float* __restrict__ var) {
    int j = threadIdx.x;
    float acc = bias[j];
    for (int k = 0; k < D; k++) {
        float s = gamma[k] * rsqrtf(var[k] + 1e-3f);
        float t = beta[k] - mean[k] * s;
        acc += t * W[k * D + j];
    }
    g_c[j] = acc;
}

// ---------------------------------------------------------------------------
// Fused kernel: (1) GEMM tile  Y = H * W'  (bf16x3 tensor-core split, fp16 out)
//               (2) scatter slice: bucket this block's edges by destination.
// The scatter phase of early-wave blocks overlaps the GEMM phase of later
// waves (same kernel -> guaranteed SM co-residency).
// ---------------------------------------------------------------------------
#define LDA2 72
#define LDW2 136
#define LDWF 136

#define A_HI 0
#define A_LO (A_HI + BROWS * LDA2)
#define W_HI (A_LO + BROWS * LDA2)
#define W_LO (W_HI + PK * LDW2)
#define SMEM_BF (W_LO + PK * LDW2)        // 35840 bf16 = 71680 B

__global__ __launch_bounds__(256, 2)
void gemm_scatter_kernel(const float* __restrict__ H,
                         const float* __restrict__ W,
                         const float* __restrict__ gamma,
                         const float* __restrict__ var,
                         const int*   __restrict__ src,
                         const int*   __restrict__ dst,
                         const float* __restrict__ ew,
                         int N, int E) {
    extern __shared__ float smf[];
    __nv_bfloat16* smb = (__nv_bfloat16*)smf;
    __shared__ float sS[D];

    int tid  = threadIdx.x;
    if (tid < D) sS[tid] = gamma[tid] * rsqrtf(var[tid] + 1e-3f);

    int row0 = blockIdx.x * BROWS;
    int wid  = tid >> 5;
    int m0   = (wid >> 1) * 32;
    int n0   = (wid & 1) * 64;

    wmma::fragment<wmma::accumulator, 16, 16, 16, float> acc[2][4];
    #pragma unroll
    for (int mf = 0; mf < 2; mf++)
        #pragma unroll
        for (int nf = 0; nf < 4; nf++) wmma::fill_fragment(acc[mf][nf], 0.0f);

    __syncthreads();

    for (int p = 0; p < 2; p++) {
        int k0 = p * PK;

        // Stage A panel (bf16 hi/lo split of H): 128 rows x 64 k.
        #pragma unroll
        for (int t = 0; t < 8; t++) {
            int i  = tid + t * 256;
            int r  = i >> 4;
            int c4 = i & 15;
            int gr = row0 + r;
            float4 v = make_float4(0.f, 0.f, 0.f, 0.f);
            if (gr < N) v = __ldg((const float4*)(H + (size_t)gr * D) + (k0 >> 2) + c4);
            __nv_bfloat16 h0 = __float2bfloat16_rn(v.x);
            __nv_bfloat16 h1 = __float2bfloat16_rn(v.y);
            __nv_bfloat16 h2 = __float2bfloat16_rn(v.z);
            __nv_bfloat16 h3 = __float2bfloat16_rn(v.w);
            __nv_bfloat16 l0 = __float2bfloat16_rn(v.x - __bfloat162float(h0));
            __nv_bfloat16 l1 = __float2bfloat16_rn(v.y - __bfloat162float(h1));
            __nv_bfloat16 l2 = __float2bfloat16_rn(v.z - __bfloat162float(h2));
            __nv_bfloat16 l3 = __float2bfloat16_rn(v.w - __bfloat162float(h3));
            int o = r * LDA2 + c4 * 4;
            *(__nv_bfloat162*)(smb + A_HI + o)     = __halves2bfloat162(h0, h1);
            *(__nv_bfloat162*)(smb + A_HI + o + 2) = __halves2bfloat162(h2, h3);
            *(__nv_bfloat162*)(smb + A_LO + o)     = __halves2bfloat162(l0, l1);
            *(__nv_bfloat162*)(smb + A_LO + o + 2) = __halves2bfloat162(l2, l3);
        }

        // Stage W' panel (scaled by s_k, bf16 hi/lo split): 64 k x 128 c.
        #pragma unroll
        for (int t = 0; t < 8; t++) {
            int i  = tid + t * 256;
            int k  = i >> 5;
            int c4 = i & 31;
            float sk = sS[k0 + k];
            float4 v = __ldg((const float4*)(W + (size_t)(k0 + k) * D) + c4);
            v.x *= sk; v.y *= sk; v.z *= sk; v.w *= sk;
            __nv_bfloat16 h0 = __float2bfloat16_rn(v.x);
            __nv_bfloat16 h1 = __float2bfloat16_rn(v.y);
            __nv_bfloat16 h2 = __float2bfloat16_rn(v.z);
            __nv_bfloat16 h3 = __float2bfloat16_rn(v.w);
            __nv_bfloat16 l0 = __float2bfloat16_rn(v.x - __bfloat162float(h0));
            __nv_bfloat16 l1 = __float2bfloat16_rn(v.y - __bfloat162float(h1));
            __nv_bfloat16 l2 = __float2bfloat16_rn(v.z - __bfloat162float(h2));
            __nv_bfloat16 l3 = __float2bfloat16_rn(v.w - __bfloat162float(h3));
            int o = k * LDW2 + c4 * 4;
            *(__nv_bfloat162*)(smb + W_HI + o)     = __halves2bfloat162(h0, h1);
            *(__nv_bfloat162*)(smb + W_HI + o + 2) = __halves2bfloat162(h2, h3);
            *(__nv_bfloat162*)(smb + W_LO + o)     = __halves2bfloat162(l0, l1);
            *(__nv_bfloat162*)(smb + W_LO + o + 2) = __halves2bfloat162(l2, l3);
        }
        __syncthreads();

        #pragma unroll
        for (int kk = 0; kk < PK / 16; kk++) {
            wmma::fragment<wmma::matrix_a, 16, 16, 16, __nv_bfloat16, wmma::row_major> aHi[2], aLo[2];
            #pragma unroll
            for (int mf = 0; mf < 2; mf++) {
                wmma::load_matrix_sync(aHi[mf], smb + A_HI + (m0 + mf * 16) * LDA2 + kk * 16, LDA2);
                wmma::load_matrix_sync(aLo[mf], smb + A_LO + (m0 + mf * 16) * LDA2 + kk * 16, LDA2);
            }
            #pragma unroll
            for (int nf = 0; nf < 4; nf++) {
                wmma::fragment<wmma::matrix_b, 16, 16, 16, __nv_bfloat16, wmma::row_major> bHi, bLo;
                wmma::load_matrix_sync(bHi, smb + W_HI + kk * 16 * LDW2 + n0 + nf * 16, LDW2);
                wmma::load_matrix_sync(bLo, smb + W_LO + kk * 16 * LDW2 + n0 + nf * 16, LDW2);
                #pragma unroll
                for (int mf = 0; mf < 2; mf++) {
                    wmma::mma_sync(acc[mf][nf], aHi[mf], bHi, acc[mf][nf]);
                    wmma::mma_sync(acc[mf][nf], aHi[mf], bLo, acc[mf][nf]);
                    wmma::mma_sync(acc[mf][nf], aLo[mf], bHi, acc[mf][nf]);
                }
            }
        }
        __syncthreads();
    }

    // GEMM epilogue: dump accs, convert to fp16 Y, store.
    #pragma unroll
    for (int mf = 0; mf < 2; mf++)
        #pragma unroll
        for (int nf = 0; nf < 4; nf++)
            wmma::store_matrix_sync(smf + (m0 + mf * 16) * LDWF + n0 + nf * 16,
                                    acc[mf][nf], LDWF, wmma::mem_row_major);
    __syncthreads();

    #pragma unroll
    for (int t = 0; t < 16; t++) {
        int i  = tid + t * 256;
        int r  = i >> 5;
        int c4 = i & 31;
        int gr = row0 + r;
        if (gr >= N) continue;
        const float* s = smf + r * LDWF + c4 * 4;
        __half2 p0 = __float22half2_rn(make_float2(s[0], s[1]));
        __half2 p1 = __float22half2_rn(make_float2(s[2], s[3]));
        uint2 u;
        u.x = *(unsigned int*)&p0;
        u.y = *(unsigned int*)&p1;
        *((uint2*)(g_Y + (size_t)gr * D) + c4) = u;
    }

    // ---- Scatter slice: this block's share of the edge list ----
    int chunk = (E + gridDim.x - 1) / gridDim.x;
    int e0 = blockIdx.x * chunk;
    int e1 = min(e0 + chunk, E);
    for (int i = e0 + tid; i < e1; i += 256) {
        int d = dst[i];
        int pos = atomicAdd(&g_cnt[d], 1);
        int s = src[i];
        float w = ew[i];
        if (pos < CAP) {
            g_edge[(size_t)d * CAP + pos] = make_int2(s, __float_as_int(w));
        } else {
            // 11-sigma unreachable: push to overflow list; gather merges it.
            int slot = atomicAdd(&g_ovf_cnt, 1);
            if (slot < OVF_CAP)
                g_ovf[slot] = make_int4(d, s, __float_as_int(w), 0);
        }
    }
}

// ---------------------------------------------------------------------------
// Gather: one warp per node; lane owns 4 columns.  Sums fp16 Y rows in fp32,
// adds c, applies exact GELU, writes the final output row.
// ---------------------------------------------------------------------------
__device__ __forceinline__ float gelu_exact(float x) {
    return 0.5f * x * (1.0f + erff(x * 0.70710678118654752f));
}

__device__ __forceinline__ void acc_row(float4& acc, int s, float w, int lane) {
    uint2 u = __ldg((const uint2*)(g_Y + (size_t)s * D) + lane);
    float2 f01 = __half22float2(*(const __half2*)&u.x);
    float2 f23 = __half22float2(*(const __half2*)&u.y);
    acc.x += w * f01.x; acc.y += w * f01.y;
    acc.z += w * f23.x; acc.w += w * f23.y;
}

__global__ __launch_bounds__(256)
void gather_kernel(float* __restrict__ out, int N) {
    int warp = (int)((blockIdx.x * (unsigned)blockDim.x + threadIdx.x) >> 5);
    int lane = threadIdx.x & 31;
    if (warp >= N) return;

    int cnt = g_cnt[warp];
    int deg = cnt < CAP ? cnt : CAP;
    const int2* lst = g_edge + (size_t)warp * CAP;

    float4 acc = make_float4(0.f, 0.f, 0.f, 0.f);

    int e = 0;
    for (; e + 4 <= deg; e += 4) {
        int4 a = __ldg((const int4*)(lst + e));
        int4 b = __ldg((const int4*)(lst + e) + 1);
        acc_row(acc, a.x, __int_as_float(a.y), lane);
        acc_row(acc, a.z, __int_as_float(a.w), lane);
        acc_row(acc, b.x, __int_as_float(b.y), lane);
        acc_row(acc, b.z, __int_as_float(b.w), lane);
    }
    for (; e < deg; e++) {
        int2 p = __ldg(lst + e);
        acc_row(acc, p.x, __int_as_float(p.y), lane);
    }

    if (cnt > CAP) {   // merge rare overflow entries (Y complete by now)
        int m = g_ovf_cnt;
        if (m > OVF_CAP) m = OVF_CAP;
        for (int i = 0; i < m; i++) {
            int4 o = g_ovf[i];
            if (o.x == warp) acc_row(acc, o.y, __int_as_float(o.z), lane);
        }
    }

    float4 c4 = __ldg((const float4*)g_c + lane);
    float4 o;
    o.x = gelu_exact(acc.x + c4.x);
    o.y = gelu_exact(acc.y + c4.y);
    o.z = gelu_exact(acc.z + c4.z);
    o.w = gelu_exact(acc.w + c4.w);
    *((float4*)(out + (size_t)warp * D) + lane) = o;
}

// ---------------------------------------------------------------------------
extern "C" void kernel_launch(void* const* d_in, const int* in_sizes, int n_in,
                              void* d_out, int out_size) {
    const float* H     = (const float*)d_in[0];
    const int*   src   = (const int*)  d_in[1];
    const int*   dst   = (const int*)  d_in[2];
    const float* ew    = (const float*)d_in[3];
    const float* gamma = (const float*)d_in[4];
    const float* beta  = (const float*)d_in[5];
    const float* mean  = (const float*)d_in[6];
    const float* var   = (const float*)d_in[7];
    const float* W     = (const float*)d_in[8];
    const float* bias  = (const float*)d_in[9];

    int N = in_sizes[0] / D;
    int E = in_sizes[1];

    zero_kernel<<<(N + 255) / 256, 256>>>(N);
    prep_c_kernel<<<1, D>>>(W, bias, gamma, beta, mean, var);

    int smem_bytes = SMEM_BF * 2;            // 71680 B
    cudaFuncSetAttribute(gemm_scatter_kernel,
                         cudaFuncAttributeMaxDynamicSharedMemorySize, smem_bytes);
    gemm_scatter_kernel<<<(N + BROWS - 1) / BROWS, 256, smem_bytes>>>(
        H, W, gamma, var, src, dst, ew, N, E);

    gather_kernel<<<(N * 32 + 255) / 256, 256>>>((float*)d_out, N);
}

// round 12
// speedup vs baseline: 1.0919x; 1.0919x over previous
#include <cuda_runtime.h>
#include <cuda_bf16.h>
#include <cuda_fp16.h>
#include <mma.h>
#include <math.h>
#include <cstdint>

using namespace nvcuda;

#define D 128
#define MAX_N 100096
#define CAP 96
#define OVF_CAP 8192
#define BROWS 128
#define PK 64                   // K panel size

// Scratch (allocation-free rule: __device__ globals).
__device__ __half  g_Y[(size_t)MAX_N * D];      // Y = H * W' in fp16
__device__ float   g_c[D];                      // c = t.W + b
__device__ int     g_cnt[MAX_N];                // per-node edge count
__device__ int2    g_edge[(size_t)MAX_N * CAP]; // buckets (src byte-offset, w-bits)
__device__ int     g_ovf_cnt;                   // overflow list count
__device__ int4    g_ovf[OVF_CAP];              // overflow (dst, src byte-off, w-bits, 0)

// ---------------------------------------------------------------------------
__global__ void zero_kernel(int n) {
    int i = blockIdx.x * blockDim.x + threadIdx.x;
    if (i < n) g_cnt[i] = 0;
    if (i == 0) g_ovf_cnt = 0;
}

// c[j] = bias[j] + sum_k (beta_k - mean_k*s_k) * W[k][j]
__global__ void prep_c_kernel(const float* __restrict__ W,
                              const float* __restrict__ bias,
                              const float* __restrict__ gamma,
                              const float* __restrict__ beta,
                              const float* __restrict__ mean,
                              const float* __restrict__ var) {
    int j = threadIdx.x;
    float acc = bias[j];
    for (int k = 0; k < D; k++) {
        float s = gamma[k] * rsqrtf(var[k] + 1e-3f);
        float t = beta[k] - mean[k] * s;
        acc += t * W[k * D + j];
    }
    g_c[j] = acc;
}

// ---------------------------------------------------------------------------
// Scatter: 4 edges per thread (vectorized edge loads, MLP=4 on the atomics).
// Buckets store the Y-row BYTE OFFSET (src*256) to kill gather address math.
// ---------------------------------------------------------------------------
__device__ __forceinline__ void scatter_one(int d, int s, float w) {
    int pos = atomicAdd(&g_cnt[d], 1);
    if (pos < CAP) {
        g_edge[(size_t)d * CAP + pos] = make_int2(s << 8, __float_as_int(w));
    } else {
        // 11-sigma unreachable: overflow list; gather merges after Y is done.
        int slot = atomicAdd(&g_ovf_cnt, 1);
        if (slot < OVF_CAP)
            g_ovf[slot] = make_int4(d, s << 8, __float_as_int(w), 0);
    }
}

__global__ void scatter_kernel(const int*   __restrict__ src,
                               const int*   __restrict__ dst,
                               const float* __restrict__ ew,
                               int E) {
    int t = blockIdx.x * blockDim.x + threadIdx.x;
    int i0 = t * 4;
    if (i0 + 3 < E) {
        int4   s4 = __ldg((const int4*)src + t);
        int4   d4 = __ldg((const int4*)dst + t);
        float4 w4 = __ldg((const float4*)ew + t);
        scatter_one(d4.x, s4.x, w4.x);
        scatter_one(d4.y, s4.y, w4.y);
        scatter_one(d4.z, s4.z, w4.z);
        scatter_one(d4.w, s4.w, w4.w);
    } else {
        for (int i = i0; i < E; i++)
            scatter_one(__ldg(dst + i), __ldg(src + i), __ldg(ew + i));
    }
}

// ---------------------------------------------------------------------------
// GEMM: Y = H * W'   (bf16x3 tensor-core split), Y stored fp16.
// ---------------------------------------------------------------------------
#define LDA2 72
#define LDW2 136
#define LDWF 136

#define A_HI 0
#define A_LO (A_HI + BROWS * LDA2)
#define W_HI (A_LO + BROWS * LDA2)
#define W_LO (W_HI + PK * LDW2)
#define SMEM_BF (W_LO + PK * LDW2)        // 35840 bf16 = 71680 B

__global__ __launch_bounds__(256, 2)
void gemm_kernel(const float* __restrict__ H,
                 const float* __restrict__ W,
                 const float* __restrict__ gamma,
                 const float* __restrict__ var,
                 int N) {
    extern __shared__ float smf[];
    __nv_bfloat16* smb = (__nv_bfloat16*)smf;
    __shared__ float sS[D];

    int tid  = threadIdx.x;
    if (tid < D) sS[tid] = gamma[tid] * rsqrtf(var[tid] + 1e-3f);

    int row0 = blockIdx.x * BROWS;
    int wid  = tid >> 5;
    int m0   = (wid >> 1) * 32;
    int n0   = (wid & 1) * 64;

    wmma::fragment<wmma::accumulator, 16, 16, 16, float> acc[2][4];
    #pragma unroll
    for (int mf = 0; mf < 2; mf++)
        #pragma unroll
        for (int nf = 0; nf < 4; nf++) wmma::fill_fragment(acc[mf][nf], 0.0f);

    __syncthreads();

    for (int p = 0; p < 2; p++) {
        int k0 = p * PK;

        #pragma unroll
        for (int t = 0; t < 8; t++) {
            int i  = tid + t * 256;
            int r  = i >> 4;
            int c4 = i & 15;
            int gr = row0 + r;
            float4 v = make_float4(0.f, 0.f, 0.f, 0.f);
            if (gr < N) v = __ldg((const float4*)(H + (size_t)gr * D) + (k0 >> 2) + c4);
            __nv_bfloat16 h0 = __float2bfloat16_rn(v.x);
            __nv_bfloat16 h1 = __float2bfloat16_rn(v.y);
            __nv_bfloat16 h2 = __float2bfloat16_rn(v.z);
            __nv_bfloat16 h3 = __float2bfloat16_rn(v.w);
            __nv_bfloat16 l0 = __float2bfloat16_rn(v.x - __bfloat162float(h0));
            __nv_bfloat16 l1 = __float2bfloat16_rn(v.y - __bfloat162float(h1));
            __nv_bfloat16 l2 = __float2bfloat16_rn(v.z - __bfloat162float(h2));
            __nv_bfloat16 l3 = __float2bfloat16_rn(v.w - __bfloat162float(h3));
            int o = r * LDA2 + c4 * 4;
            *(__nv_bfloat162*)(smb + A_HI + o)     = __halves2bfloat162(h0, h1);
            *(__nv_bfloat162*)(smb + A_HI + o + 2) = __halves2bfloat162(h2, h3);
            *(__nv_bfloat162*)(smb + A_LO + o)     = __halves2bfloat162(l0, l1);
            *(__nv_bfloat162*)(smb + A_LO + o + 2) = __halves2bfloat162(l2, l3);
        }

        #pragma unroll
        for (int t = 0; t < 8; t++) {
            int i  = tid + t * 256;
            int k  = i >> 5;
            int c4 = i & 31;
            float sk = sS[k0 + k];
            float4 v = __ldg((const float4*)(W + (size_t)(k0 + k) * D) + c4);
            v.x *= sk; v.y *= sk; v.z *= sk; v.w *= sk;
            __nv_bfloat16 h0 = __float2bfloat16_rn(v.x);
            __nv_bfloat16 h1 = __float2bfloat16_rn(v.y);
            __nv_bfloat16 h2 = __float2bfloat16_rn(v.z);
            __nv_bfloat16 h3 = __float2bfloat16_rn(v.w);
            __nv_bfloat16 l0 = __float2bfloat16_rn(v.x - __bfloat162float(h0));
            __nv_bfloat16 l1 = __float2bfloat16_rn(v.y - __bfloat162float(h1));
            __nv_bfloat16 l2 = __float2bfloat16_rn(v.z - __bfloat162float(h2));
            __nv_bfloat16 l3 = __float2bfloat16_rn(v.w - __bfloat162float(h3));
            int o = k * LDW2 + c4 * 4;
            *(__nv_bfloat162*)(smb + W_HI + o)     = __halves2bfloat162(h0, h1);
            *(__nv_bfloat162*)(smb + W_HI + o + 2) = __halves2bfloat162(h2, h3);
            *(__nv_bfloat162*)(smb + W_LO + o)     = __halves2bfloat162(l0, l1);
            *(__nv_bfloat162*)(smb + W_LO + o + 2) = __halves2bfloat162(l2, l3);
        }
        __syncthreads();

        #pragma unroll
        for (int kk = 0; kk < PK / 16; kk++) {
            wmma::fragment<wmma::matrix_a, 16, 16, 16, __nv_bfloat16, wmma::row_major> aHi[2], aLo[2];
            #pragma unroll
            for (int mf = 0; mf < 2; mf++) {
                wmma::load_matrix_sync(aHi[mf], smb + A_HI + (m0 + mf * 16) * LDA2 + kk * 16, LDA2);
                wmma::load_matrix_sync(aLo[mf], smb + A_LO + (m0 + mf * 16) * LDA2 + kk * 16, LDA2);
            }
            #pragma unroll
            for (int nf = 0; nf < 4; nf++) {
                wmma::fragment<wmma::matrix_b, 16, 16, 16, __nv_bfloat16, wmma::row_major> bHi, bLo;
                wmma::load_matrix_sync(bHi, smb + W_HI + kk * 16 * LDW2 + n0 + nf * 16, LDW2);
                wmma::load_matrix_sync(bLo, smb + W_LO + kk * 16 * LDW2 + n0 + nf * 16, LDW2);
                #pragma unroll
                for (int mf = 0; mf < 2; mf++) {
                    wmma::mma_sync(acc[mf][nf], aHi[mf], bHi, acc[mf][nf]);
                    wmma::mma_sync(acc[mf][nf], aHi[mf], bLo, acc[mf][nf]);
                    wmma::mma_sync(acc[mf][nf], aLo[mf], bHi, acc[mf][nf]);
                }
            }
        }
        __syncthreads();
    }

    #pragma unroll
    for (int mf = 0; mf < 2; mf++)
        #pragma unroll
        for (int nf = 0; nf < 4; nf++)
            wmma::store_matrix_sync(smf + (m0 + mf * 16) * LDWF + n0 + nf * 16,
                                    acc[mf][nf], LDWF, wmma::mem_row_major);
    __syncthreads();

    #pragma unroll
    for (int t = 0; t < 16; t++) {
        int i  = tid + t * 256;
        int r  = i >> 5;
        int c4 = i & 31;
        int gr = row0 + r;
        if (gr >= N) continue;
        const float* s = smf + r * LDWF + c4 * 4;
        __half2 p0 = __float22half2_rn(make_float2(s[0], s[1]));
        __half2 p1 = __float22half2_rn(make_float2(s[2], s[3]));
        uint2 u;
        u.x = *(unsigned int*)&p0;
        u.y = *(unsigned int*)&p1;
        *((uint2*)(g_Y + (size_t)gr * D) + c4) = u;
    }
}

// ---------------------------------------------------------------------------
// Gather: one warp per node; lane owns 4 columns.  Buckets carry byte
// offsets; accumulation uses packed fma.rn.f32x2 (2 instr for 4 columns).
// ---------------------------------------------------------------------------
__device__ __forceinline__ float gelu_exact(float x) {
    return 0.5f * x * (1.0f + erff(x * 0.70710678118654752f));
}

__device__ __forceinline__ void acc_row(unsigned long long& a01,
                                        unsigned long long& a23,
                                        int byteoff, float w, int lane) {
    uint2 u = __ldg((const uint2*)((const char*)g_Y + byteoff) + lane);
    float2 f01 = __half22float2(*(const __half2*)&u.x);
    float2 f23 = __half22float2(*(const __half2*)&u.y);
    unsigned long long w2, y01, y23;
    asm("mov.b64 %0, {%1, %1};" : "=l"(w2)  : "f"(w));
    asm("mov.b64 %0, {%1, %2};" : "=l"(y01) : "f"(f01.x), "f"(f01.y));
    asm("mov.b64 %0, {%1, %2};" : "=l"(y23) : "f"(f23.x), "f"(f23.y));
    asm("fma.rn.f32x2 %0, %1, %2, %0;" : "+l"(a01) : "l"(y01), "l"(w2));
    asm("fma.rn.f32x2 %0, %1, %2, %0;" : "+l"(a23) : "l"(y23), "l"(w2));
}

__global__ __launch_bounds__(256)
void gather_kernel(float* __restrict__ out, int N) {
    int warp = (int)((blockIdx.x * (unsigned)blockDim.x + threadIdx.x) >> 5);
    int lane = threadIdx.x & 31;
    if (warp >= N) return;

    int cnt = g_cnt[warp];
    int deg = cnt < CAP ? cnt : CAP;
    const int2* lst = g_edge + (size_t)warp * CAP;

    unsigned long long a01 = 0ull, a23 = 0ull;   // packed f32x2 accumulators

    int e = 0;
    for (; e + 4 <= deg; e += 4) {
        int4 a = __ldg((const int4*)(lst + e));
        int4 b = __ldg((const int4*)(lst + e) + 1);
        acc_row(a01, a23, a.x, __int_as_float(a.y), lane);
        acc_row(a01, a23, a.z, __int_as_float(a.w), lane);
        acc_row(a01, a23, b.x, __int_as_float(b.y), lane);
        acc_row(a01, a23, b.z, __int_as_float(b.w), lane);
    }
    for (; e < deg; e++) {
        int2 p = __ldg(lst + e);
        acc_row(a01, a23, p.x, __int_as_float(p.y), lane);
    }

    if (cnt > CAP) {   // merge rare overflow entries (Y complete by now)
        int m = g_ovf_cnt;
        if (m > OVF_CAP) m = OVF_CAP;
        for (int i = 0; i < m; i++) {
            int4 o = g_ovf[i];
            if (o.x == warp) acc_row(a01, a23, o.y, __int_as_float(o.z), lane);
        }
    }

    float ax, ay, az, aw;
    asm("mov.b64 {%0, %1}, %2;" : "=f"(ax), "=f"(ay) : "l"(a01));
    asm("mov.b64 {%0, %1}, %2;" : "=f"(az), "=f"(aw) : "l"(a23));

    float4 c4 = __ldg((const float4*)g_c + lane);
    float4 o;
    o.x = gelu_exact(ax + c4.x);
    o.y = gelu_exact(ay + c4.y);
    o.z = gelu_exact(az + c4.z);
    o.w = gelu_exact(aw + c4.w);
    *((float4*)(out + (size_t)warp * D) + lane) = o;
}

// ---------------------------------------------------------------------------
// Stream fork: scatter (side stream) overlaps gemm (main stream).
// ---------------------------------------------------------------------------
static cudaStream_t s_side = 0;
static cudaEvent_t  s_e0 = 0, s_e1 = 0;

extern "C" void kernel_launch(void* const* d_in, const int* in_sizes, int n_in,
                              void* d_out, int out_size) {
    const float* H     = (const float*)d_in[0];
    const int*   src   = (const int*)  d_in[1];
    const int*   dst   = (const int*)  d_in[2];
    const float* ew    = (const float*)d_in[3];
    const float* gamma = (const float*)d_in[4];
    const float* beta  = (const float*)d_in[5];
    const float* mean  = (const float*)d_in[6];
    const float* var   = (const float*)d_in[7];
    const float* W     = (const float*)d_in[8];
    const float* bias  = (const float*)d_in[9];

    int N = in_sizes[0] / D;
    int E = in_sizes[1];

    if (s_side == 0) {
        cudaStreamCreateWithFlags(&s_side, cudaStreamNonBlocking);
        cudaEventCreateWithFlags(&s_e0, cudaEventDisableTiming);
        cudaEventCreateWithFlags(&s_e1, cudaEventDisableTiming);
    }

    zero_kernel<<<(N + 255) / 256, 256>>>(N);
    prep_c_kernel<<<1, D>>>(W, bias, gamma, beta, mean, var);

    // Fork: scatter on side stream (independent of gemm).
    cudaEventRecord(s_e0, 0);
    cudaStreamWaitEvent(s_side, s_e0, 0);
    int sblocks = (E / 4 + 255) / 256 + 1;
    scatter_kernel<<<sblocks, 256, 0, s_side>>>(src, dst, ew, E);

    int smem_bytes = SMEM_BF * 2;            // 71680 B
    cudaFuncSetAttribute(gemm_kernel,
                         cudaFuncAttributeMaxDynamicSharedMemorySize, smem_bytes);
    gemm_kernel<<<(N + BROWS - 1) / BROWS, 256, smem_bytes>>>(H, W, gamma, var, N);

    // Join: gather needs both gemm (main) and scatter (side).
    cudaEventRecord(s_e1, s_side);
    cudaStreamWaitEvent(0, s_e1, 0);
    gather_kernel<<<(N * 32 + 255) / 256, 256>>>((float*)d_out, N);
}